// round 7
// baseline (speedup 1.0000x reference)
#include <cuda_runtime.h>
#include <cfloat>

#define S_LEN    2560
#define THREADS  320            // 320 threads x 8 elements = 2560
#define EPT      8              // elements per thread
#define NWARPS   (THREADS / 32) // 10
#define LAST_T   (THREADS - 1)

// ---------------------------------------------------------------------------
// Fused block reduction: NS sums + NM maxes in one barrier sequence.
// scratch must hold NWARPS * (NS + NM) floats. Results broadcast to all.
// ---------------------------------------------------------------------------
template <int NS, int NM>
__device__ __forceinline__ void block_reduce_fused(float* sums, float* maxes,
                                                   float* scratch) {
    #pragma unroll
    for (int o = 16; o > 0; o >>= 1) {
        #pragma unroll
        for (int k = 0; k < NS; ++k)
            sums[k] += __shfl_down_sync(0xffffffffu, sums[k], o);
        #pragma unroll
        for (int k = 0; k < NM; ++k)
            maxes[k] = fmaxf(maxes[k], __shfl_down_sync(0xffffffffu, maxes[k], o));
    }
    const int warp = threadIdx.x >> 5;
    const int lane = threadIdx.x & 31;
    if (lane == 0) {
        #pragma unroll
        for (int k = 0; k < NS; ++k) scratch[warp * (NS + NM) + k] = sums[k];
        #pragma unroll
        for (int k = 0; k < NM; ++k) scratch[warp * (NS + NM) + NS + k] = maxes[k];
    }
    __syncthreads();
    if (warp == 0) {
        #pragma unroll
        for (int k = 0; k < NS; ++k) {
            float v = (lane < NWARPS) ? scratch[lane * (NS + NM) + k] : 0.0f;
            #pragma unroll
            for (int o = 8; o > 0; o >>= 1)
                v += __shfl_down_sync(0xffffffffu, v, o);
            if (lane == 0) scratch[k] = v;
        }
        #pragma unroll
        for (int k = 0; k < NM; ++k) {
            float v = (lane < NWARPS) ? scratch[lane * (NS + NM) + NS + k] : -FLT_MAX;
            #pragma unroll
            for (int o = 8; o > 0; o >>= 1)
                v = fmaxf(v, __shfl_down_sync(0xffffffffu, v, o));
            if (lane == 0) scratch[NS + k] = v;
        }
    }
    __syncthreads();
    #pragma unroll
    for (int k = 0; k < NS; ++k) sums[k] = scratch[k];
    #pragma unroll
    for (int k = 0; k < NM; ++k) maxes[k] = scratch[NS + k];
    __syncthreads();  // protect scratch before reuse
}

template <int N>
__device__ __forceinline__ void block_reduce_sum(float* vals, float* scratch) {
    #pragma unroll
    for (int o = 16; o > 0; o >>= 1)
        #pragma unroll
        for (int k = 0; k < N; ++k)
            vals[k] += __shfl_down_sync(0xffffffffu, vals[k], o);

    const int warp = threadIdx.x >> 5;
    const int lane = threadIdx.x & 31;
    if (lane == 0) {
        #pragma unroll
        for (int k = 0; k < N; ++k) scratch[warp * N + k] = vals[k];
    }
    __syncthreads();
    if (warp == 0) {
        #pragma unroll
        for (int k = 0; k < N; ++k) {
            float v = (lane < NWARPS) ? scratch[lane * N + k] : 0.0f;
            #pragma unroll
            for (int o = 8; o > 0; o >>= 1)
                v += __shfl_down_sync(0xffffffffu, v, o);
            if (lane == 0) scratch[k] = v;
        }
    }
    __syncthreads();
    #pragma unroll
    for (int k = 0; k < N; ++k) vals[k] = scratch[k];
    __syncthreads();
}

__device__ __forceinline__ float sgnf(float x) {
    return (x > 0.0f) ? 1.0f : ((x < 0.0f) ? -1.0f : 0.0f);
}

// ---------------------------------------------------------------------------
// One CTA per row. Each thread holds 8 contiguous elements in REGISTERS
// (2 x LDG.128) plus a 2-element halo (1 x LDG.64, hits L1 via neighbor's
// line). All statistics computed from registers; SMEM only for reduction
// scratch + 4 edge values.
// Hjorth first-moment sums are telescoped (exact): sum(d1) = x[S-1]-x[0],
// sum(d2) = d1[S-2]-d1[0].
// ---------------------------------------------------------------------------
__global__ __launch_bounds__(THREADS)
void health_stats_kernel(const float* __restrict__ in,
                         float* __restrict__ out) {
    __shared__ float scratch[NWARPS * 9];
    __shared__ float edge[4];   // x[0], x[1], x[S-2], x[S-1]

    const int b = blockIdx.x;
    const int t = threadIdx.x;
    const float* row = in + (size_t)b * S_LEN;

    // ---- Load 8 elements + 2-element halo into registers -------------------
    float x[EPT];
    {
        const float4 v0 = *reinterpret_cast<const float4*>(row + EPT * t);
        const float4 v1 = *reinterpret_cast<const float4*>(row + EPT * t + 4);
        x[0] = v0.x; x[1] = v0.y; x[2] = v0.z; x[3] = v0.w;
        x[4] = v1.x; x[5] = v1.y; x[6] = v1.z; x[7] = v1.w;
    }
    const bool has_halo = (t < LAST_T);
    float x8 = 0.0f, x9 = 0.0f;
    if (has_halo) {
        const float2 h = *reinterpret_cast<const float2*>(row + EPT * t + 8);
        x8 = h.x; x9 = h.y;
    }
    if (t == 0)      { edge[0] = x[0]; edge[1] = x[1]; }
    if (t == LAST_T) { edge[2] = x[6]; edge[3] = x[7]; }

    // ---- Pass A (registers): raw sums + extrema + zcr + Hjorth sq-sums -----
    // acc: [0]=sum [1]=sumsq [2]=abssum [3]=zc [4]=sumsq_d1 [5]=sumsq_d2
    float acc[6];
    #pragma unroll
    for (int k = 0; k < 6; ++k) acc[k] = 0.0f;
    float mx[3];  // [0]=max(x) [1]=max(-x) [2]=max(|x|)
    mx[0] = -FLT_MAX; mx[1] = -FLT_MAX; mx[2] = 0.0f;

    float sg[EPT];
    #pragma unroll
    for (int j = 0; j < EPT; ++j) {
        const float e  = x[j];
        const float ae = fabsf(e);
        acc[0] += e;
        acc[1] += e * e;
        acc[2] += ae;
        mx[0] = fmaxf(mx[0], e);
        mx[1] = fmaxf(mx[1], -e);
        mx[2] = fmaxf(mx[2], ae);
        sg[j] = sgnf(e);
    }

    // d1[j] = x[j+1]-x[j]; j=0..6 always in-register, j=7 needs halo
    float d1[EPT];
    #pragma unroll
    for (int j = 0; j < EPT - 1; ++j) d1[j] = x[j + 1] - x[j];
    d1[7] = x8 - x[7];
    const float d1_8 = x9 - x8;

    #pragma unroll
    for (int j = 0; j < EPT - 1; ++j) {      // 7 always-valid pairs
        acc[3] += (sg[j] != sg[j + 1]) ? 1.0f : 0.0f;
        acc[4] += d1[j] * d1[j];
    }
    #pragma unroll
    for (int j = 0; j < EPT - 2; ++j) {      // 6 always-valid d2
        const float dd = d1[j + 1] - d1[j];
        acc[5] += dd * dd;
    }
    if (has_halo) {
        acc[3] += (sg[7] != sgnf(x8)) ? 1.0f : 0.0f;
        acc[4] += d1[7] * d1[7];
        const float dd6 = d1[7] - d1[6];
        const float dd7 = d1_8 - d1[7];
        acc[5] += dd6 * dd6 + dd7 * dd7;
    }

    block_reduce_fused<6, 3>(acc, mx, scratch);

    const float n      = (float)S_LEN;
    const float sum    = acc[0];
    const float sumsq  = acc[1];
    const float abssum = acc[2];
    const float zc     = acc[3];
    const float sqd1   = acc[4];
    const float sqd2   = acc[5];
    const float maximum = mx[0];
    const float minimum = -mx[1];
    const float absmax  = mx[2];

    // telescoped Hjorth first moments (exact)
    const float sd1 = edge[3] - edge[0];
    const float sd2 = (edge[3] - edge[2]) - (edge[1] - edge[0]);

    const float mean = sum / n;

    // ---- Pass B (registers): centered moments (exact two-pass) -------------
    float c[3];  // sum c^2, c^3, c^4
    c[0] = c[1] = c[2] = 0.0f;
    #pragma unroll
    for (int j = 0; j < EPT; ++j) {
        const float cc = x[j] - mean;
        const float q  = cc * cc;
        c[0] += q;
        c[1] += q * cc;
        c[2] += q * q;
    }
    block_reduce_sum<3>(c, scratch);

    const float var = c[0] / (n - 1.0f);     // unbiased
    const float std = sqrtf(var);

    // ---- Pass C (registers): outlier count with exact std ------------------
    float outl[1];
    outl[0] = 0.0f;
    const float thr = 3.0f * std;
    #pragma unroll
    for (int j = 0; j < EPT; ++j)
        outl[0] += (fabsf(x[j] - mean) > thr) ? 1.0f : 0.0f;
    block_reduce_sum<1>(outl, scratch);

    // ---- Final scalars ------------------------------------------------------
    if (t == 0) {
        const float rms      = sqrtf(sumsq / n);
        const float skewness = (c[1] / n) / (std * std * std);
        const float kurtosis = (c[2] / n) / (var * var);
        const float shape    = rms * n / abssum;
        const float impulse  = absmax * n / abssum;
        const float zcr      = zc / (2.0f * n);

        const float n1 = n - 1.0f;           // #d1 = 2559
        const float n2 = n - 2.0f;           // #d2 = 2558
        const float var_d1 = (sqd1 - sd1 * sd1 / n1) / (n1 - 1.0f);
        const float var_d2 = (sqd2 - sd2 * sd2 / n2) / (n2 - 1.0f);
        const float mobility   = sqrtf(var_d1 / var);
        const float complexity = sqrtf(var_d2 / var_d1);

        float* o = out + (size_t)b * 15;
        o[0]  = mean;
        o[1]  = maximum;
        o[2]  = minimum;
        o[3]  = maximum - minimum;
        o[4]  = var;
        o[5]  = rms;
        o[6]  = skewness;
        o[7]  = kurtosis;
        o[8]  = shape;
        o[9]  = impulse;
        o[10] = outl[0];
        o[11] = zcr;
        o[12] = var;          // activity
        o[13] = mobility;
        o[14] = complexity;
    }
}

extern "C" void kernel_launch(void* const* d_in, const int* in_sizes, int n_in,
                              void* d_out, int out_size) {
    const float* in  = (const float*)d_in[0];
    float* out       = (float*)d_out;
    const int B = in_sizes[0] / S_LEN;   // 16384 rows
    health_stats_kernel<<<B, THREADS>>>(in, out);
}